// round 14
// baseline (speedup 1.0000x reference)
#include <cuda_runtime.h>
#include <cstdint>

#define NN      131071
#define NSTEPS  335
#define QLB     1e-4f
#define FULLM   0xFFFFFFFFu

// doorbells: flag(high 32) | float bits(low 32), one word per (step, node)
__device__ unsigned long long g1[NSTEPS * 8192];  // level-3 roots
__device__ unsigned long long g2[NSTEPS * 512];   // level-7 roots
__device__ unsigned long long g3[NSTEPS * 32];    // level-11 roots
__device__ unsigned long long g4[NSTEPS * 2];     // level-15 roots
__device__ int gprog;                              // T5 progress (backpressure)

__global__ void init_kernel() {
    int i = blockIdx.x * blockDim.x + threadIdx.x;
    if (i < NSTEPS * 8192) g1[i] = 0ull;
    if (i < NSTEPS * 512)  g2[i] = 0ull;
    if (i < NSTEPS * 32)   g3[i] = 0ull;
    if (i < NSTEPS * 2)    g4[i] = 0ull;
    if (i == 0)            gprog = 0;
}

__device__ __forceinline__ float ex2f(float x) {
    float r; asm("ex2.approx.ftz.f32 %0, %1;" : "=f"(r) : "f"(x)); return r;
}

struct NodeC {
    float lgA, pexp, inv_ns, wet_c, tw, ssx2, a1len, a2len;
};

__device__ __forceinline__ NodeC make_node(int g,
    const float* __restrict__ nr,  const float* __restrict__ qsr,
    const float* __restrict__ len, const float* __restrict__ slope,
    const float* __restrict__ twp, const float* __restrict__ ssp,
    const float* __restrict__ xp)
{
    NodeC c;
    float n  = fmaf(nr[g], 0.34f, 0.01f);
    float qs = 3.0f * qsr[g];
    float s0 = fmaxf(slope[g], 1e-4f);
    float sq = sqrtf(s0);
    float den = fmaf(21.0f, sq, 1e-8f);
    c.lgA    = __log2f(n * (qs + 1.0f) / den);
    c.pexp   = 3.0f / fmaf(3.0f, qs, 5.0f);
    c.inv_ns = sq / n;
    float ssv = ssp[g];
    c.wet_c  = 2.0f * sqrtf(fmaf(ssv, ssv, 1.0f));
    c.tw     = twp[g];
    c.ssx2   = 2.0f * ssv;
    float L  = len[g];
    float xv = xp[g];
    c.a1len = 2.0f * (1.0f - xv) * L;
    c.a2len = 2.0f * xv * L;
    return c;
}

// dv = DT*(5/3)*v_clip = 6000*v_clip; r = 1/(dv+a1len);
// c1=(dv-a2len)r; c2=(dv+a2len)r; c4=2dv*r; c3=1-c4
__device__ __forceinline__ void phase_a(const NodeC& c, float q, float it, float qpc,
                                        float& b, float& c1)
{
    float depth  = fmaxf(ex2f(c.pexp * (__log2f(q) + c.lgA)), 0.01f);
    float bottom = fmaxf(fmaf(-c.ssx2, depth, c.tw), 0.1f);
    float area   = (c.tw + bottom) * (0.5f * depth);
    float wetted = fmaf(depth, c.wet_c, bottom);
    float v      = c.inv_ns * ex2f(0.66666668f * (__log2f(area) - __log2f(wetted)));
    v = fminf(fmaxf(v, 0.3f), 15.0f);
    float dv = 6000.0f * v;
    float r  = __fdividef(1.0f, dv + c.a1len);
    c1       = (dv - c.a2len) * r;
    float c2 = (dv + c.a2len) * r;
    float c4 = (2.0f * dv) * r;
    float c3 = 1.0f - c4;
    b = fmaf(c2, it, fmaf(c3, q, c4 * qpc));
}

// 4-level slabs. T1: levels 0-3, TWO subtrees per warp (halves: lanes 0-14 / 16-30).
// T2: levels 4-7 (512 warps), T3: 8-11 (32), T4: 12-15 (2), T5: level 16 (1).
// i_t captured from sweep shuffles. Per-step release/acquire doorbells.
// T1 runahead bounded to <=96+32 steps past T5 (keeps doorbell polls L2-hot).
__global__ void __launch_bounds__(32)
route_kernel(const float* __restrict__ qp,
             const float* __restrict__ nr,  const float* __restrict__ qsr,
             const float* __restrict__ len, const float* __restrict__ slope,
             const float* __restrict__ twp, const float* __restrict__ ssp,
             const float* __restrict__ xp,  float* __restrict__ out)
{
    const int w    = blockIdx.x;          // 0..4642
    const int lane = threadIdx.x;

    int tier, sub;
    if      (w >= 547) { tier = 1; sub = w - 547; }   // 4096
    else if (w >= 35)  { tier = 2; sub = w - 35;  }   // 512
    else if (w >= 3)   { tier = 3; sub = w - 3;   }   // 32
    else if (w >= 1)   { tier = 4; sub = w - 1;   }   // 2
    else               { tier = 5; sub = 0;       }   // 1

    bool is_node = false, is_poll = false, has_it = true;
    int  gid = 0, sweepd = 99;
    int  sA = 0, sB = 1;
    const unsigned long long* pollp = 0; int pollstride = 0;
    unsigned long long* pubp = 0; int pubstride = 0;
    bool do_pub = false;

    if (tier == 1) {
        const int half = lane >> 4, ll = lane & 15;
        if (ll < 15) {
            is_node = true;
            int dh = 31 - __clz(ll + 1);              // 0..3; dh==3 are leaves (level 0)
            int j  = ll + 1 - (1 << dh);
            int r  = 2 * sub + half;                  // level-3 root index
            gid = 131072 - (1 << (14 + dh)) + (r << dh) + j;
            if (dh == 3) has_it = false; else sweepd = dh;
        }
        sA = min(2 * ll + 1, 15) + (half << 4);
        sB = min(2 * ll + 2, 15) + (half << 4);
        do_pub = (ll == 0) && is_node;
        pubp = g1 + 2 * sub + half; pubstride = 8192;
    } else {
        const int rl    = (tier == 2) ? 7 : (tier == 3) ? 11 : (tier == 4) ? 15 : 16;
        const int nnode = (tier == 5) ? 1 : 15;
        const int npoll = (tier == 5) ? 2 : 16;
        if (lane < nnode) {
            is_node = true;
            int dh = 31 - __clz(lane + 1);            // 0..3
            int j  = lane + 1 - (1 << dh);
            gid = 131072 - (1 << (17 - rl + dh)) + (sub << dh) + j;
            sweepd = dh;
        }
        is_poll = (lane >= 16) && (lane < 16 + npoll);
        if (tier == 5)                      { sA = 16; sB = 17; }
        else if (lane >= 7 && lane <= 14)   { sA = 2 * lane + 2; sB = 2 * lane + 3; }
        else                                { sA = min(2 * lane + 1, 31); sB = min(2 * lane + 2, 31); }
        const int c = lane - 16;
        if      (tier == 2) { pollp = g1 + sub * 16 + c; pollstride = 8192; pubp = g2 + sub; pubstride = 512; }
        else if (tier == 3) { pollp = g2 + sub * 16 + c; pollstride = 512;  pubp = g3 + sub; pubstride = 32;  }
        else if (tier == 4) { pollp = g3 + sub * 16 + c; pollstride = 32;   pubp = g4 + sub; pubstride = 2;   }
        else                { pollp = g4 + c;            pollstride = 2;    }
        do_pub = (tier != 5) && (lane == 0);
    }

    NodeC cN;
    float cq = 0.0f, qnext_raw = 0.0f, itn = 0.0f;
    if (is_node) {
        cN = make_node(gid, nr, qsr, len, slope, twp, ssp, xp);
        cq = qp[gid];                                  // q0 raw (no clamp)
        qnext_raw = cq;                                // row 0 for step 0
    }
    if (is_poll) {
        const int c = lane - 16;
        int cgid;
        if      (tier == 2) cgid = 131072 - (1 << 14) + sub * 16 + c;   // level 3
        else if (tier == 3) cgid = 131072 - (1 << 10) + sub * 16 + c;   // level 7
        else if (tier == 4) cgid = 131072 - (1 << 6)  + sub * 16 + c;   // level 11
        else                cgid = 131072 - 4 + c;                      // level 15
        cq = qp[cgid];                                 // child q0 raw
    }
    if (tier == 5 && lane == 0) out[0] = fmaxf(qp[NN - 1], QLB);

    // priming: step-0 i_t from children's raw q0 (matches reference semantics)
    {
        float itA = __shfl_sync(FULLM, cq, sA);
        float itB = __shfl_sync(FULLM, cq, sB);
        itn = itA + itB;
    }

    for (int t = 0; t < NSTEPS; ++t) {
        // ---- T1 runahead bound: keep doorbell window L2-hot ----
        if (tier == 1 && (t & 31) == 0 && t >= 128) {
            for (;;) {
                int pg;
                asm volatile("ld.relaxed.gpu.global.b32 %0, [%1];"
                             : "=r"(pg) : "l"(&gprog) : "memory");
                if (t - pg <= 96) break;
                __nanosleep(256);
            }
        }

        float qpc = fmaxf(qnext_raw, QLB);
        if (is_node) {                                 // issue next step's load
            int tn = (t + 1 < NSTEPS) ? t + 1 : t;
            qnext_raw = __ldg(qp + (size_t)tn * NN + gid);
        }
        float b = 0.0f, c1 = 0.0f;
        if (is_node) {
            phase_a(cN, cq, has_it ? itn : 0.0f, qpc, b, c1);
        }
        if (is_poll) {                                 // fetch this step's child root (raw)
            unsigned long long v;
            do {
                asm volatile("ld.acquire.gpu.global.b64 %0, [%1];"
                             : "=l"(v) : "l"(pollp) : "memory");
            } while ((v >> 32) == 0ull);
            b = __uint_as_float((unsigned)v);
            pollp += pollstride;
        }
        // bottom-up sweep on raw values; capture next step's i_t from children
        if (tier == 1) {
            #pragma unroll
            for (int d = 2; d >= 0; --d) {
                float bl = __shfl_sync(FULLM, b, sA);
                float br = __shfl_sync(FULLM, b, sB);
                if (sweepd == d) {
                    b = fmaf(c1, bl + br, b);
                    itn = fmaxf(bl, QLB) + fmaxf(br, QLB);
                }
            }
        } else {
            #pragma unroll
            for (int d = 3; d >= 0; --d) {
                float bl = __shfl_sync(FULLM, b, sA);
                float br = __shfl_sync(FULLM, b, sB);
                if (sweepd == d) {
                    b = fmaf(c1, bl + br, b);
                    itn = fmaxf(bl, QLB) + fmaxf(br, QLB);
                }
            }
        }
        if (do_pub) {
            unsigned long long pv = (1ull << 32) | (unsigned long long)__float_as_uint(b);
            asm volatile("st.release.gpu.global.b64 [%0], %1;"
                         :: "l"(pubp), "l"(pv) : "memory");
            pubp += pubstride;
        }
        if (tier == 5 && lane == 0) {
            out[t + 1] = fmaxf(b, QLB);
            asm volatile("st.relaxed.gpu.global.b32 [%0], %1;"
                         :: "l"(&gprog), "r"(t) : "memory");
        }
        cq = fmaxf(b, QLB);                            // own carry
    }
}

extern "C" void kernel_launch(void* const* d_in, const int* in_sizes, int n_in,
                              void* d_out, int out_size)
{
    const float* qp    = (const float*)d_in[0];
    const float* nr    = (const float*)d_in[1];
    const float* qsr   = (const float*)d_in[2];
    const float* len   = (const float*)d_in[3];
    const float* slope = (const float*)d_in[4];
    const float* twp   = (const float*)d_in[5];
    const float* ssp   = (const float*)d_in[6];
    const float* xp    = (const float*)d_in[7];
    float* out = (float*)d_out;

    init_kernel<<<(NSTEPS * 8192 + 255) / 256, 256>>>();
    route_kernel<<<4643, 32>>>(qp, nr, qsr, len, slope, twp, ssp, xp, out);
}

// round 15
// speedup vs baseline: 1.3480x; 1.3480x over previous
#include <cuda_runtime.h>
#include <cstdint>

#define NN      131071
#define NSTEPS  335
#define QLB     1e-4f
#define FULLM   0xFFFFFFFFu

// doorbells: flag(high 32) | float bits(low 32), one word per (step, node)
__device__ unsigned long long g1[NSTEPS * 2048];  // level-5 roots
__device__ unsigned long long g2[NSTEPS * 32];    // level-11 roots

__global__ void init_kernel() {
    int i = blockIdx.x * blockDim.x + threadIdx.x;
    if (i < NSTEPS * 2048) g1[i] = 0ull;
    if (i < NSTEPS * 32)   g2[i] = 0ull;
}

__device__ __forceinline__ float ex2f(float x) {
    float r; asm("ex2.approx.ftz.f32 %0, %1;" : "=f"(r) : "f"(x)); return r;
}

struct NodeC {
    float lgA, pexp, inv_ns, wet_c, tw, ssx2, a1len, a2len;
};

__device__ __forceinline__ NodeC make_node(int g,
    const float* __restrict__ nr,  const float* __restrict__ qsr,
    const float* __restrict__ len, const float* __restrict__ slope,
    const float* __restrict__ twp, const float* __restrict__ ssp,
    const float* __restrict__ xp)
{
    NodeC c;
    float n  = fmaf(nr[g], 0.34f, 0.01f);
    float qs = 3.0f * qsr[g];
    float s0 = fmaxf(slope[g], 1e-4f);
    float sq = sqrtf(s0);
    float den = fmaf(21.0f, sq, 1e-8f);
    c.lgA    = __log2f(n * (qs + 1.0f) / den);
    c.pexp   = 3.0f / fmaf(3.0f, qs, 5.0f);
    c.inv_ns = sq / n;
    float ssv = ssp[g];
    c.wet_c  = 2.0f * sqrtf(fmaf(ssv, ssv, 1.0f));
    c.tw     = twp[g];
    c.ssx2   = 2.0f * ssv;
    float L  = len[g];
    float xv = xp[g];
    c.a1len = 2.0f * (1.0f - xv) * L;
    c.a2len = 2.0f * xv * L;
    return c;
}

// dv = DT*(5/3)*v_clip = 6000*v_clip; r = 1/(dv+a1len);
// c1=(dv-a2len)r; c2=(dv+a2len)r; c4=2dv*r; c3=1-c4
__device__ __forceinline__ void phase_a(const NodeC& c, float q, float it, float qpc,
                                        float& b, float& c1)
{
    float depth  = fmaxf(ex2f(c.pexp * (__log2f(q) + c.lgA)), 0.01f);
    float bottom = fmaxf(fmaf(-c.ssx2, depth, c.tw), 0.1f);
    float area   = (c.tw + bottom) * (0.5f * depth);
    float wetted = fmaf(depth, c.wet_c, bottom);
    float v      = c.inv_ns * ex2f(0.66666668f * (__log2f(area) - __log2f(wetted)));
    v = fminf(fmaxf(v, 0.3f), 15.0f);
    float dv = 6000.0f * v;
    float r  = __fdividef(1.0f, dv + c.a1len);
    c1       = (dv - c.a2len) * r;
    float c2 = (dv + c.a2len) * r;
    float c4 = (2.0f * dv) * r;
    float c3 = 1.0f - c4;
    b = fmaf(c2, it, fmaf(c3, q, c4 * qpc));
}

// T1 (w 0..1023): two level-5 subtrees (levels 0-5, 126 nodes). Lane = leaf pair +
//   L1 parent (in-lane) + one upper node (L2-L5) per 16-lane half. 8 SHFL/step.
// T2 (w 1024..1055): levels 6-11 of one level-11 subtree. Lane = one L6 node
//   (polls its own 2 level-5 children) + one upper node (L7-L11).
// T3 (w 1056): levels 12-16. Lanes 0-15 = L12 (poll 2 level-11 roots each);
//   lanes 16-30 = upper (L13-L16); root lane writes out.
__global__ void __launch_bounds__(32)
route_kernel(const float* __restrict__ qp,
             const float* __restrict__ nr,  const float* __restrict__ qsr,
             const float* __restrict__ len, const float* __restrict__ slope,
             const float* __restrict__ twp, const float* __restrict__ ssp,
             const float* __restrict__ xp,  float* __restrict__ out)
{
    const int w    = blockIdx.x;
    const int lane = threadIdx.x;

    if (w < 1024) {
        // ================= T1 =================
        const int h = lane >> 4, u = lane & 15;
        const bool has_up = (u != 15);
        const int gidA = 64 * w + 2 * lane;            // leaf (level 0)
        const int gidB = gidA + 1;
        const int gidL = 65536 + 32 * w + lane;        // L1
        int gidU = 0, du = 0, gc0 = 0;
        if (has_up) {
            du = 31 - __clz(u + 1);                    // 0=L5,1=L4,2=L3,3=L2
            int idx = (1 << du) * (2 * w + h) + (u + 1 - (1 << du));
            gidU = 131072 - (1 << (12 + du)) + idx;
            gc0  = 131072 - (1 << (13 + du)) + 2 * idx;   // children gids
        }
        NodeC cA = make_node(gidA, nr, qsr, len, slope, twp, ssp, xp);
        NodeC cB = make_node(gidB, nr, qsr, len, slope, twp, ssp, xp);
        NodeC cL = make_node(gidL, nr, qsr, len, slope, twp, ssp, xp);
        NodeC cU;
        if (has_up) cU = make_node(gidU, nr, qsr, len, slope, twp, ssp, xp);

        float qA = qp[gidA], qB = qp[gidB], qL = qp[gidL];     // raw q0 carries
        float qU = has_up ? qp[gidU] : 1.0f;
        float itL = qA + qB;                                    // step-0 i_t (raw q0)
        float itU = has_up ? (qp[gc0] + qp[gc0 + 1]) : 0.0f;
        float pA = qA, pB = qB, pL = qL, pU = qU;               // row-0 prefetch

        int sCa = lane, sCb = lane;                             // L2 capture (from q1L)
        if (has_up && du == 3) { int j = u - 7; sCa = 16 * h + 2 * j; sCb = sCa + 1; }
        int sUa = lane, sUb = lane;                             // L3-L5 (from bU)
        if (has_up && du <= 2) { sUa = 16 * h + 2 * u + 1; sUb = sUa + 1; }

        unsigned long long* pub = g1 + 2 * w + h;               // lanes with u==0

        for (int t = 0; t < NSTEPS; ++t) {
            float qpA_ = fmaxf(pA, QLB), qpB_ = fmaxf(pB, QLB);
            float qpL_ = fmaxf(pL, QLB), qpU_ = fmaxf(pU, QLB);
            {
                int tn = (t + 1 < NSTEPS) ? t + 1 : t;
                const float* row = qp + (size_t)tn * NN;
                pA = __ldg(row + gidA); pB = __ldg(row + gidB);
                pL = __ldg(row + gidL);
                if (has_up) pU = __ldg(row + gidU);
            }
            float bA, bB, bL, bU = 0.0f, c1A, c1B, c1L, c1U = 0.0f;
            phase_a(cA, qA, 0.0f, qpA_, bA, c1A);               // leaves: i_t = 0
            phase_a(cB, qB, 0.0f, qpB_, bB, c1B);
            phase_a(cL, qL, itL,  qpL_, bL, c1L);
            if (has_up) phase_a(cU, qU, itU, qpU_, bU, c1U);
            // in-lane sweep: leaves final = b; L1 final:
            float q1L = fmaf(c1L, bA + bB, bL);
            itL = fmaxf(bA, QLB) + fmaxf(bB, QLB);
            qA = fmaxf(bA, QLB); qB = fmaxf(bB, QLB);
            qL = fmaxf(q1L, QLB);
            // L2 capture (children = L1 q1, raw)
            {
                float xa = __shfl_sync(FULLM, q1L, sCa);
                float xb = __shfl_sync(FULLM, q1L, sCb);
                if (has_up && du == 3) {
                    bU = fmaf(c1U, xa + xb, bU);
                    itU = fmaxf(xa, QLB) + fmaxf(xb, QLB);
                }
            }
            // L3..L5 sweep on bU
            #pragma unroll
            for (int d = 2; d >= 0; --d) {
                float ya = __shfl_sync(FULLM, bU, sUa);
                float yb = __shfl_sync(FULLM, bU, sUb);
                if (has_up && du == d) {
                    bU = fmaf(c1U, ya + yb, bU);
                    itU = fmaxf(ya, QLB) + fmaxf(yb, QLB);
                }
            }
            if (has_up) qU = fmaxf(bU, QLB);
            if (u == 0) {                                       // lanes 0,16: L5 roots
                unsigned long long pv = (1ull << 32) | (unsigned long long)__float_as_uint(bU);
                asm volatile("st.release.gpu.global.b64 [%0], %1;"
                             :: "l"(pub), "l"(pv) : "memory");
                pub += 2048;
            }
        }
    } else if (w < 1056) {
        // ================= T2 =================
        const int sub = w - 1024;
        const bool has_up = (lane != 31);
        const int gid6 = 129024 + 32 * sub + lane;              // L6
        int gidU = 0, du = 0, gc0 = 0;
        if (has_up) {
            du = 31 - __clz(lane + 1);                          // 0=L11 .. 4=L7
            int idx = (1 << du) * sub + (lane + 1 - (1 << du));
            gidU = 131072 - (1 << (6 + du)) + idx;
            gc0  = 131072 - (1 << (7 + du)) + 2 * idx;
        }
        NodeC c6 = make_node(gid6, nr, qsr, len, slope, twp, ssp, xp);
        NodeC cU;
        if (has_up) cU = make_node(gidU, nr, qsr, len, slope, twp, ssp, xp);

        float q6 = qp[gid6];
        float qU = has_up ? qp[gidU] : 1.0f;
        float rA = qp[126976 + 64 * sub + 2 * lane];            // level-5 q0 raw
        float rB = qp[126976 + 64 * sub + 2 * lane + 1];
        float it6 = rA + rB;
        float itU = has_up ? (qp[gc0] + qp[gc0 + 1]) : 0.0f;
        float p6 = q6, pU = qU;

        int sCa = lane, sCb = lane;                             // L7 capture (from q16)
        if (has_up && du == 4) { int j = lane - 15; sCa = 2 * j; sCb = 2 * j + 1; }
        int sUa = lane, sUb = lane;                             // L8-L11 (from bU)
        if (has_up && du <= 3) { sUa = 2 * lane + 1; sUb = sUa + 1; }

        const unsigned long long* poll = g1 + 64 * sub + 2 * lane;
        unsigned long long* pub = g2 + sub;

        for (int t = 0; t < NSTEPS; ++t) {
            float qp6_ = fmaxf(p6, QLB), qpU_ = fmaxf(pU, QLB);
            {
                int tn = (t + 1 < NSTEPS) ? t + 1 : t;
                const float* row = qp + (size_t)tn * NN;
                p6 = __ldg(row + gid6);
                if (has_up) pU = __ldg(row + gidU);
            }
            float b6, c16, bU = 0.0f, c1U = 0.0f;
            phase_a(c6, q6, it6, qp6_, b6, c16);
            if (has_up) phase_a(cU, qU, itU, qpU_, bU, c1U);
            // poll own 2 level-5 children for step t (raw swept roots)
            unsigned long long vA, vB;
            do {
                asm volatile("ld.acquire.gpu.global.b64 %0, [%1];"
                             : "=l"(vA) : "l"(poll) : "memory");
                asm volatile("ld.acquire.gpu.global.b64 %0, [%1];"
                             : "=l"(vB) : "l"(poll + 1) : "memory");
            } while ((vA >> 32) == 0ull || (vB >> 32) == 0ull);
            rA = __uint_as_float((unsigned)vA);
            rB = __uint_as_float((unsigned)vB);
            poll += 2048;
            float q16 = fmaf(c16, rA + rB, b6);                 // L6 final (raw)
            it6 = fmaxf(rA, QLB) + fmaxf(rB, QLB);
            q6 = fmaxf(q16, QLB);
            // L7 capture from L6 q1
            {
                float xa = __shfl_sync(FULLM, q16, sCa);
                float xb = __shfl_sync(FULLM, q16, sCb);
                if (has_up && du == 4) {
                    bU = fmaf(c1U, xa + xb, bU);
                    itU = fmaxf(xa, QLB) + fmaxf(xb, QLB);
                }
            }
            #pragma unroll
            for (int d = 3; d >= 0; --d) {
                float ya = __shfl_sync(FULLM, bU, sUa);
                float yb = __shfl_sync(FULLM, bU, sUb);
                if (has_up && du == d) {
                    bU = fmaf(c1U, ya + yb, bU);
                    itU = fmaxf(ya, QLB) + fmaxf(yb, QLB);
                }
            }
            if (has_up) qU = fmaxf(bU, QLB);
            if (lane == 0) {                                    // L11 root
                unsigned long long pv = (1ull << 32) | (unsigned long long)__float_as_uint(bU);
                asm volatile("st.release.gpu.global.b64 [%0], %1;"
                             :: "l"(pub), "l"(pv) : "memory");
                pub += 32;
            }
        }
    } else {
        // ================= T3 =================
        const bool isL = (lane < 16);
        const bool isU = (lane >= 16 && lane < 31);
        int gid = 0, du = 0, gc0 = 0;
        if (isL) gid = 131040 + lane;                           // L12
        if (isU) {
            int u = lane - 16;
            du = 31 - __clz(u + 1);                             // 0=L16 .. 3=L13
            int idx = u + 1 - (1 << du);
            gid = 131072 - (1 << (1 + du)) + idx;
            gc0 = 131072 - (1 << (2 + du)) + 2 * idx;
        }
        NodeC cN;
        if (isL || isU) cN = make_node(gid, nr, qsr, len, slope, twp, ssp, xp);
        float q = (isL || isU) ? qp[gid] : 1.0f;
        float rA = 0.0f, rB = 0.0f, itn = 0.0f;
        if (isL) {
            rA = qp[131008 + 2 * lane]; rB = qp[131008 + 2 * lane + 1];   // level-11 q0
            itn = rA + rB;
        }
        if (isU) itn = qp[gc0] + qp[gc0 + 1];
        float p = q;

        int sCa = lane, sCb = lane;                             // L13 capture (from L12 q1)
        if (isU && du == 3) { int j = lane - 23; sCa = 2 * j; sCb = 2 * j + 1; }
        int sUa = lane, sUb = lane;                             // L14-L16 (from b)
        if (isU && du <= 2) { int u = lane - 16; sUa = 16 + 2 * u + 1; sUb = sUa + 1; }

        const unsigned long long* poll = g2 + 2 * lane;
        if (lane == 0) out[0] = fmaxf(qp[131070], QLB);

        for (int t = 0; t < NSTEPS; ++t) {
            float qpc = fmaxf(p, QLB);
            {
                int tn = (t + 1 < NSTEPS) ? t + 1 : t;
                if (isL || isU) p = __ldg(qp + (size_t)tn * NN + gid);
            }
            float b = 0.0f, c1 = 0.0f;
            if (isL || isU) phase_a(cN, q, itn, qpc, b, c1);
            float q1n = b;
            if (isL) {                                          // poll own 2 level-11 roots
                unsigned long long vA, vB;
                do {
                    asm volatile("ld.acquire.gpu.global.b64 %0, [%1];"
                                 : "=l"(vA) : "l"(poll) : "memory");
                    asm volatile("ld.acquire.gpu.global.b64 %0, [%1];"
                                 : "=l"(vB) : "l"(poll + 1) : "memory");
                } while ((vA >> 32) == 0ull || (vB >> 32) == 0ull);
                rA = __uint_as_float((unsigned)vA);
                rB = __uint_as_float((unsigned)vB);
                poll += 32;
                q1n = fmaf(c1, rA + rB, b);                     // L12 final (raw)
                itn = fmaxf(rA, QLB) + fmaxf(rB, QLB);
                q = fmaxf(q1n, QLB);
            }
            {
                float xa = __shfl_sync(FULLM, q1n, sCa);
                float xb = __shfl_sync(FULLM, q1n, sCb);
                if (isU && du == 3) {
                    b = fmaf(c1, xa + xb, b);
                    itn = fmaxf(xa, QLB) + fmaxf(xb, QLB);
                }
            }
            #pragma unroll
            for (int d = 2; d >= 0; --d) {
                float ya = __shfl_sync(FULLM, b, sUa);
                float yb = __shfl_sync(FULLM, b, sUb);
                if (isU && du == d) {
                    b = fmaf(c1, ya + yb, b);
                    itn = fmaxf(ya, QLB) + fmaxf(yb, QLB);
                }
            }
            if (isU) q = fmaxf(b, QLB);
            if (lane == 16) out[t + 1] = fmaxf(b, QLB);         // L16 root
        }
    }
}

extern "C" void kernel_launch(void* const* d_in, const int* in_sizes, int n_in,
                              void* d_out, int out_size)
{
    const float* qp    = (const float*)d_in[0];
    const float* nr    = (const float*)d_in[1];
    const float* qsr   = (const float*)d_in[2];
    const float* len   = (const float*)d_in[3];
    const float* slope = (const float*)d_in[4];
    const float* twp   = (const float*)d_in[5];
    const float* ssp   = (const float*)d_in[6];
    const float* xp    = (const float*)d_in[7];
    float* out = (float*)d_out;

    init_kernel<<<(NSTEPS * 2048 + 255) / 256, 256>>>();
    route_kernel<<<1057, 32>>>(qp, nr, qsr, len, slope, twp, ssp, xp, out);
}

// round 16
// speedup vs baseline: 1.6334x; 1.2117x over previous
#include <cuda_runtime.h>
#include <cstdint>

#define NN      131071
#define NSTEPS  335
#define QLB     1e-4f
#define FULLM   0xFFFFFFFFu

// doorbells: flag(high 32) | float bits(low 32), one word per (step, node)
__device__ unsigned long long g1[NSTEPS * 8192];  // level-3 roots
__device__ unsigned long long g2[NSTEPS * 128];   // level-9 roots
__device__ unsigned long long g3[NSTEPS * 2];     // level-15 roots

__global__ void init_kernel() {
    int i = blockIdx.x * blockDim.x + threadIdx.x;
    if (i < NSTEPS * 8192) g1[i] = 0ull;
    if (i < NSTEPS * 128)  g2[i] = 0ull;
    if (i < NSTEPS * 2)    g3[i] = 0ull;
}

__device__ __forceinline__ float ex2f(float x) {
    float r; asm("ex2.approx.ftz.f32 %0, %1;" : "=f"(r) : "f"(x)); return r;
}

struct NodeC {
    float lgA, pexp, inv_ns, wet_c, tw, ssx2, a1len, a2len;
};

__device__ __forceinline__ NodeC make_node(int g,
    const float* __restrict__ nr,  const float* __restrict__ qsr,
    const float* __restrict__ len, const float* __restrict__ slope,
    const float* __restrict__ twp, const float* __restrict__ ssp,
    const float* __restrict__ xp)
{
    NodeC c;
    float n  = fmaf(nr[g], 0.34f, 0.01f);
    float qs = 3.0f * qsr[g];
    float s0 = fmaxf(slope[g], 1e-4f);
    float sq = sqrtf(s0);
    float den = fmaf(21.0f, sq, 1e-8f);
    c.lgA    = __log2f(n * (qs + 1.0f) / den);
    c.pexp   = 3.0f / fmaf(3.0f, qs, 5.0f);
    c.inv_ns = sq / n;
    float ssv = ssp[g];
    c.wet_c  = 2.0f * sqrtf(fmaf(ssv, ssv, 1.0f));
    c.tw     = twp[g];
    c.ssx2   = 2.0f * ssv;
    float L  = len[g];
    float xv = xp[g];
    c.a1len = 2.0f * (1.0f - xv) * L;
    c.a2len = 2.0f * xv * L;
    return c;
}

// dv = DT*(5/3)*v_clip = 6000*v_clip; r = 1/(dv+a1len);
// c1=(dv-a2len)r; c2=(dv+a2len)r; c4=2dv*r; c3=1-c4
__device__ __forceinline__ void phase_a(const NodeC& c, float q, float it, float qpc,
                                        float& b, float& c1)
{
    float depth  = fmaxf(ex2f(c.pexp * (__log2f(q) + c.lgA)), 0.01f);
    float bottom = fmaxf(fmaf(-c.ssx2, depth, c.tw), 0.1f);
    float area   = (c.tw + bottom) * (0.5f * depth);
    float wetted = fmaf(depth, c.wet_c, bottom);
    float v      = c.inv_ns * ex2f(0.66666668f * (__log2f(area) - __log2f(wetted)));
    v = fminf(fmaxf(v, 0.3f), 15.0f);
    float dv = 6000.0f * v;
    float r  = __fdividef(1.0f, dv + c.a1len);
    c1       = (dv - c.a2len) * r;
    float c2 = (dv + c.a2len) * r;
    float c4 = (2.0f * dv) * r;
    float c3 = 1.0f - c4;
    b = fmaf(c2, it, fmaf(c3, q, c4 * qpc));
}

// T1 (w 0..4095): R13 tier-1 — levels 0-3, TWO subtrees/warp (halves 0-14/16-30),
//   1 node/lane, fused i_t, 6 SHFL/step, publishes 2 level-3 roots.
// T2 (w 4096..4223): levels 4-9 of a level-9 subtree. EVERY lane owns an L4 node
//   and polls its own 2 level-3 children; lanes 0-30 also own one upper (L5-L9).
// T3 (w 4224..4225): levels 10-15 (same shape as T2 over g2).
// T4 (w 4226): level 16; lane 0 polls the 2 level-15 roots, writes out.
__global__ void __launch_bounds__(32)
route_kernel(const float* __restrict__ qp,
             const float* __restrict__ nr,  const float* __restrict__ qsr,
             const float* __restrict__ len, const float* __restrict__ slope,
             const float* __restrict__ twp, const float* __restrict__ ssp,
             const float* __restrict__ xp,  float* __restrict__ out)
{
    const int w    = blockIdx.x;
    const int lane = threadIdx.x;

    if (w < 4096) {
        // ================= T1 (R13 tier-1, proven 0.98 us/step) =================
        const int half = lane >> 4, ll = lane & 15;
        const bool is_node = (ll < 15);
        bool has_it = true;
        int gid = 0, sweepd = 99;
        if (is_node) {
            int dh = 31 - __clz(ll + 1);              // 0..3; dh==3 are leaves (level 0)
            int j  = ll + 1 - (1 << dh);
            int r  = 2 * w + half;                    // level-3 root index
            gid = 131072 - (1 << (14 + dh)) + (r << dh) + j;
            if (dh == 3) has_it = false; else sweepd = dh;
        }
        const int sA = min(2 * ll + 1, 15) + (half << 4);
        const int sB = min(2 * ll + 2, 15) + (half << 4);
        const bool do_pub = (ll == 0);
        unsigned long long* pubp = g1 + 2 * w + half;

        NodeC cN;
        float cq = 0.0f, qnext_raw = 0.0f, itn = 0.0f;
        if (is_node) {
            cN = make_node(gid, nr, qsr, len, slope, twp, ssp, xp);
            cq = qp[gid];                              // q0 raw
            qnext_raw = cq;                            // row 0 for step 0
        }
        {   // priming i_t from children's raw q0
            float itA = __shfl_sync(FULLM, cq, sA);
            float itB = __shfl_sync(FULLM, cq, sB);
            itn = itA + itB;
        }
        for (int t = 0; t < NSTEPS; ++t) {
            float qpc = fmaxf(qnext_raw, QLB);
            if (is_node) {
                int tn = (t + 1 < NSTEPS) ? t + 1 : t;
                qnext_raw = __ldg(qp + (size_t)tn * NN + gid);
            }
            float b = 0.0f, c1 = 0.0f;
            if (is_node) phase_a(cN, cq, has_it ? itn : 0.0f, qpc, b, c1);
            #pragma unroll
            for (int d = 2; d >= 0; --d) {
                float bl = __shfl_sync(FULLM, b, sA);
                float br = __shfl_sync(FULLM, b, sB);
                if (sweepd == d) {
                    b = fmaf(c1, bl + br, b);
                    itn = fmaxf(bl, QLB) + fmaxf(br, QLB);
                }
            }
            if (do_pub) {
                unsigned long long pv = (1ull << 32) | (unsigned long long)__float_as_uint(b);
                asm volatile("st.release.gpu.global.b64 [%0], %1;"
                             :: "l"(pubp), "l"(pv) : "memory");
                pubp += 8192;
            }
            cq = fmaxf(b, QLB);
        }
    } else if (w < 4226) {
        // ================= T2 / T3 (identical shape, different level base) =======
        // T2: base level 4 (sub 0..127, consumes g1, publishes g2)
        // T3: base level 10 (sub 0..1, consumes g2, publishes g3)
        const bool isT2 = (w < 4224);
        const int sub   = isT2 ? (w - 4096) : (w - 4224);
        const int bL    = isT2 ? 4 : 10;               // owned-lane level
        // OFFS[l] = 131072 - 2^(17-l)
        const int offL  = 131072 - (1 << (17 - bL));           // owned level base
        const int offC  = 131072 - (1 << (18 - bL));           // child level base
        const int gidL  = offL + 32 * sub + lane;
        const bool has_up = (lane < 31);
        int gidU = 0, du = 0, gc0 = 0;
        if (has_up) {
            du = 31 - __clz(lane + 1);                 // 0=top(L9/L15) .. 4=L5/L11
            int idx = (1 << du) * sub + (lane + 1 - (1 << du));
            gidU = 131072 - (1 << (12 - bL + du)) + idx;       // level (bL+5)-du
            gc0  = 131072 - (1 << (13 - bL + du)) + 2 * idx;   // its children
        }
        NodeC cL = make_node(gidL, nr, qsr, len, slope, twp, ssp, xp);
        NodeC cU;
        if (has_up) cU = make_node(gidU, nr, qsr, len, slope, twp, ssp, xp);

        float qL = qp[gidL];
        float qU = has_up ? qp[gidU] : 1.0f;
        float rA = qp[offC + 64 * sub + 2 * lane];     // child q0 raw
        float rB = qp[offC + 64 * sub + 2 * lane + 1];
        float itL = rA + rB;
        float itU = has_up ? (qp[gc0] + qp[gc0 + 1]) : 0.0f;
        float pL = qL, pU = qU;

        int sCa = lane, sCb = lane;                    // du==4 capture (from q1L)
        if (has_up && du == 4) { int j = lane - 15; sCa = 2 * j; sCb = 2 * j + 1; }
        int sUa = lane, sUb = lane;                    // du<=3 sweep (from bU)
        if (has_up && du <= 3) { sUa = 2 * lane + 1; sUb = sUa + 1; }

        const unsigned long long* poll =
            (isT2 ? g1 : g2) + 64 * sub + 2 * lane;
        const int pollstride = isT2 ? 8192 : 128;
        unsigned long long* pub = (isT2 ? g2 : g3) + sub;
        const int pubstride = isT2 ? 128 : 2;

        for (int t = 0; t < NSTEPS; ++t) {
            float qpL_ = fmaxf(pL, QLB), qpU_ = fmaxf(pU, QLB);
            {
                int tn = (t + 1 < NSTEPS) ? t + 1 : t;
                const float* row = qp + (size_t)tn * NN;
                pL = __ldg(row + gidL);
                if (has_up) pU = __ldg(row + gidU);
            }
            float bL_, c1L, bU = 0.0f, c1U = 0.0f;
            phase_a(cL, qL, itL, qpL_, bL_, c1L);
            if (has_up) phase_a(cU, qU, itU, qpU_, bU, c1U);
            // poll own 2 children for step t (raw swept roots)
            unsigned long long vA, vB;
            do {
                asm volatile("ld.acquire.gpu.global.b64 %0, [%1];"
                             : "=l"(vA) : "l"(poll) : "memory");
                asm volatile("ld.acquire.gpu.global.b64 %0, [%1];"
                             : "=l"(vB) : "l"(poll + 1) : "memory");
            } while ((vA >> 32) == 0ull || (vB >> 32) == 0ull);
            rA = __uint_as_float((unsigned)vA);
            rB = __uint_as_float((unsigned)vB);
            poll += pollstride;
            float q1L = fmaf(c1L, rA + rB, bL_);       // owned-level final (raw)
            itL = fmaxf(rA, QLB) + fmaxf(rB, QLB);
            qL = fmaxf(q1L, QLB);
            // capture for du==4 from q1L
            {
                float xa = __shfl_sync(FULLM, q1L, sCa);
                float xb = __shfl_sync(FULLM, q1L, sCb);
                if (has_up && du == 4) {
                    bU = fmaf(c1U, xa + xb, bU);
                    itU = fmaxf(xa, QLB) + fmaxf(xb, QLB);
                }
            }
            #pragma unroll
            for (int d = 3; d >= 0; --d) {
                float ya = __shfl_sync(FULLM, bU, sUa);
                float yb = __shfl_sync(FULLM, bU, sUb);
                if (has_up && du == d) {
                    bU = fmaf(c1U, ya + yb, bU);
                    itU = fmaxf(ya, QLB) + fmaxf(yb, QLB);
                }
            }
            if (has_up) qU = fmaxf(bU, QLB);
            if (lane == 0) {                           // subtree root (L9 / L15)
                unsigned long long pv = (1ull << 32) | (unsigned long long)__float_as_uint(bU);
                asm volatile("st.release.gpu.global.b64 [%0], %1;"
                             :: "l"(pub), "l"(pv) : "memory");
                pub += pubstride;
            }
            qL = qL;  // keep
        }
    } else {
        // ================= T4: level 16 root =================
        if (lane != 0) return;
        const int gid = 131070;
        NodeC cR = make_node(gid, nr, qsr, len, slope, twp, ssp, xp);
        float q = qp[gid];
        float rA = qp[131068], rB = qp[131069];        // level-15 q0 raw
        float itn = rA + rB;
        float p = q;
        const unsigned long long* poll = g3;
        out[0] = fmaxf(qp[131070], QLB);

        for (int t = 0; t < NSTEPS; ++t) {
            float qpc = fmaxf(p, QLB);
            {
                int tn = (t + 1 < NSTEPS) ? t + 1 : t;
                p = __ldg(qp + (size_t)tn * NN + gid);
            }
            float b, c1;
            phase_a(cR, q, itn, qpc, b, c1);
            unsigned long long vA, vB;
            do {
                asm volatile("ld.acquire.gpu.global.b64 %0, [%1];"
                             : "=l"(vA) : "l"(poll) : "memory");
                asm volatile("ld.acquire.gpu.global.b64 %0, [%1];"
                             : "=l"(vB) : "l"(poll + 1) : "memory");
            } while ((vA >> 32) == 0ull || (vB >> 32) == 0ull);
            rA = __uint_as_float((unsigned)vA);
            rB = __uint_as_float((unsigned)vB);
            poll += 2;
            float q1 = fmaf(c1, rA + rB, b);           // root final (raw)
            itn = fmaxf(rA, QLB) + fmaxf(rB, QLB);
            q = fmaxf(q1, QLB);
            out[t + 1] = q;
        }
    }
}

extern "C" void kernel_launch(void* const* d_in, const int* in_sizes, int n_in,
                              void* d_out, int out_size)
{
    const float* qp    = (const float*)d_in[0];
    const float* nr    = (const float*)d_in[1];
    const float* qsr   = (const float*)d_in[2];
    const float* len   = (const float*)d_in[3];
    const float* slope = (const float*)d_in[4];
    const float* twp   = (const float*)d_in[5];
    const float* ssp   = (const float*)d_in[6];
    const float* xp    = (const float*)d_in[7];
    float* out = (float*)d_out;

    init_kernel<<<(NSTEPS * 8192 + 255) / 256, 256>>>();
    route_kernel<<<4227, 32>>>(qp, nr, qsr, len, slope, twp, ssp, xp, out);
}

// round 17
// speedup vs baseline: 2.8104x; 1.7206x over previous
#include <cuda_runtime.h>
#include <cstdint>

#define NN      131071
#define NSTEPS  335
#define QLB     1e-4f
#define FULLM   0xFFFFFFFFu

// doorbells: flag(high 32) | float bits(low 32), one word per (step, node).
// Payload and flag share one aligned 64-bit word -> relaxed atomics suffice
// (single-copy atomicity); no release/acquire ordering needed.
__device__ unsigned long long g1[NSTEPS * 8192];  // level-3 roots
__device__ unsigned long long g2[NSTEPS * 128];   // level-9 roots
__device__ unsigned long long g3[NSTEPS * 2];     // level-15 roots

__global__ void init_kernel() {
    int i = blockIdx.x * blockDim.x + threadIdx.x;
    if (i < NSTEPS * 8192) g1[i] = 0ull;
    if (i < NSTEPS * 128)  g2[i] = 0ull;
    if (i < NSTEPS * 2)    g3[i] = 0ull;
}

__device__ __forceinline__ float ex2f(float x) {
    float r; asm("ex2.approx.ftz.f32 %0, %1;" : "=f"(r) : "f"(x)); return r;
}

__device__ __forceinline__ void pub_relaxed(unsigned long long* p, float b) {
    unsigned long long pv = (1ull << 32) | (unsigned long long)__float_as_uint(b);
    asm volatile("st.relaxed.gpu.global.b64 [%0], %1;" :: "l"(p), "l"(pv) : "memory");
}

struct NodeC {
    float lgA, pexp, inv_ns, wet_c, tw, ssx2, a1len, a2len;
};

__device__ __forceinline__ NodeC make_node(int g,
    const float* __restrict__ nr,  const float* __restrict__ qsr,
    const float* __restrict__ len, const float* __restrict__ slope,
    const float* __restrict__ twp, const float* __restrict__ ssp,
    const float* __restrict__ xp)
{
    NodeC c;
    float n  = fmaf(nr[g], 0.34f, 0.01f);
    float qs = 3.0f * qsr[g];
    float s0 = fmaxf(slope[g], 1e-4f);
    float sq = sqrtf(s0);
    float den = fmaf(21.0f, sq, 1e-8f);
    c.lgA    = __log2f(n * (qs + 1.0f) / den);
    c.pexp   = 3.0f / fmaf(3.0f, qs, 5.0f);
    c.inv_ns = sq / n;
    float ssv = ssp[g];
    c.wet_c  = 2.0f * sqrtf(fmaf(ssv, ssv, 1.0f));
    c.tw     = twp[g];
    c.ssx2   = 2.0f * ssv;
    float L  = len[g];
    float xv = xp[g];
    c.a1len = 2.0f * (1.0f - xv) * L;
    c.a2len = 2.0f * xv * L;
    return c;
}

// dv = DT*(5/3)*v_clip = 6000*v_clip; r = 1/(dv+a1len);
// c1=(dv-a2len)r; c2=(dv+a2len)r; c4=2dv*r; c3=1-c4
__device__ __forceinline__ void phase_a(const NodeC& c, float q, float it, float qpc,
                                        float& b, float& c1)
{
    float depth  = fmaxf(ex2f(c.pexp * (__log2f(q) + c.lgA)), 0.01f);
    float bottom = fmaxf(fmaf(-c.ssx2, depth, c.tw), 0.1f);
    float area   = (c.tw + bottom) * (0.5f * depth);
    float wetted = fmaf(depth, c.wet_c, bottom);
    float v      = c.inv_ns * ex2f(0.66666668f * (__log2f(area) - __log2f(wetted)));
    v = fminf(fmaxf(v, 0.3f), 15.0f);
    float dv = 6000.0f * v;
    float r  = __fdividef(1.0f, dv + c.a1len);
    c1       = (dv - c.a2len) * r;
    float c2 = (dv + c.a2len) * r;
    float c4 = (2.0f * dv) * r;
    float c3 = 1.0f - c4;
    b = fmaf(c2, it, fmaf(c3, q, c4 * qpc));
}

// T1 (w 0..4095): levels 0-3, TWO subtrees/warp (halves 0-14/16-30),
//   1 node/lane, fused i_t, 6 SHFL/step, publishes 2 level-3 roots.
// T2 (w 4096..4223): levels 4-9 of a level-9 subtree. EVERY lane owns an L4 node
//   and polls its own 2 level-3 children; lanes 0-30 also own one upper (L5-L9).
// T3 (w 4224..4225): levels 10-15 (same shape over g2).
// T4 (w 4226): level 16; lane 0 polls the 2 level-15 roots, writes out.
__global__ void __launch_bounds__(32)
route_kernel(const float* __restrict__ qp,
             const float* __restrict__ nr,  const float* __restrict__ qsr,
             const float* __restrict__ len, const float* __restrict__ slope,
             const float* __restrict__ twp, const float* __restrict__ ssp,
             const float* __restrict__ xp,  float* __restrict__ out)
{
    const int w    = blockIdx.x;
    const int lane = threadIdx.x;

    if (w < 4096) {
        // ================= T1 =================
        const int half = lane >> 4, ll = lane & 15;
        const bool is_node = (ll < 15);
        bool has_it = true;
        int gid = 0, sweepd = 99;
        if (is_node) {
            int dh = 31 - __clz(ll + 1);              // 0..3; dh==3 are leaves (level 0)
            int j  = ll + 1 - (1 << dh);
            int r  = 2 * w + half;                    // level-3 root index
            gid = 131072 - (1 << (14 + dh)) + (r << dh) + j;
            if (dh == 3) has_it = false; else sweepd = dh;
        }
        const int sA = min(2 * ll + 1, 15) + (half << 4);
        const int sB = min(2 * ll + 2, 15) + (half << 4);
        const bool do_pub = (ll == 0);
        unsigned long long* pubp = g1 + 2 * w + half;

        NodeC cN;
        float cq = 0.0f, qnext_raw = 0.0f, itn = 0.0f;
        if (is_node) {
            cN = make_node(gid, nr, qsr, len, slope, twp, ssp, xp);
            cq = qp[gid];                              // q0 raw
            qnext_raw = cq;                            // row 0 for step 0
        }
        {   // priming i_t from children's raw q0
            float itA = __shfl_sync(FULLM, cq, sA);
            float itB = __shfl_sync(FULLM, cq, sB);
            itn = itA + itB;
        }
        for (int t = 0; t < NSTEPS; ++t) {
            float qpc = fmaxf(qnext_raw, QLB);
            if (is_node) {
                int tn = (t + 1 < NSTEPS) ? t + 1 : t;
                qnext_raw = __ldg(qp + (size_t)tn * NN + gid);
            }
            float b = 0.0f, c1 = 0.0f;
            if (is_node) phase_a(cN, cq, has_it ? itn : 0.0f, qpc, b, c1);
            #pragma unroll
            for (int d = 2; d >= 0; --d) {
                float bl = __shfl_sync(FULLM, b, sA);
                float br = __shfl_sync(FULLM, b, sB);
                if (sweepd == d) {
                    b = fmaf(c1, bl + br, b);
                    itn = fmaxf(bl, QLB) + fmaxf(br, QLB);
                }
            }
            if (do_pub) {
                pub_relaxed(pubp, b);
                pubp += 8192;
            }
            cq = fmaxf(b, QLB);
        }
    } else if (w < 4226) {
        // ================= T2 / T3 =================
        const bool isT2 = (w < 4224);
        const int sub   = isT2 ? (w - 4096) : (w - 4224);
        const int bL    = isT2 ? 4 : 10;               // owned-lane level
        const int offL  = 131072 - (1 << (17 - bL));   // owned level base
        const int offC  = 131072 - (1 << (18 - bL));   // child level base
        const int gidL  = offL + 32 * sub + lane;
        const bool has_up = (lane < 31);
        int gidU = 0, du = 0, gc0 = 0;
        if (has_up) {
            du = 31 - __clz(lane + 1);                 // 0=top .. 4=bL+1
            int idx = (1 << du) * sub + (lane + 1 - (1 << du));
            gidU = 131072 - (1 << (12 - bL + du)) + idx;
            gc0  = 131072 - (1 << (13 - bL + du)) + 2 * idx;
        }
        NodeC cL = make_node(gidL, nr, qsr, len, slope, twp, ssp, xp);
        NodeC cU;
        if (has_up) cU = make_node(gidU, nr, qsr, len, slope, twp, ssp, xp);

        float qL = qp[gidL];
        float qU = has_up ? qp[gidU] : 1.0f;
        float rA = qp[offC + 64 * sub + 2 * lane];     // child q0 raw
        float rB = qp[offC + 64 * sub + 2 * lane + 1];
        float itL = rA + rB;
        float itU = has_up ? (qp[gc0] + qp[gc0 + 1]) : 0.0f;
        float pL = qL, pU = qU;

        int sCa = lane, sCb = lane;                    // du==4 capture (from q1L)
        if (has_up && du == 4) { int j = lane - 15; sCa = 2 * j; sCb = 2 * j + 1; }
        int sUa = lane, sUb = lane;                    // du<=3 sweep (from bU)
        if (has_up && du <= 3) { sUa = 2 * lane + 1; sUb = sUa + 1; }

        const unsigned long long* poll =
            (isT2 ? g1 : g2) + 64 * sub + 2 * lane;
        const int pollstride = isT2 ? 8192 : 128;
        unsigned long long* pub = (isT2 ? g2 : g3) + sub;
        const int pubstride = isT2 ? 128 : 2;

        for (int t = 0; t < NSTEPS; ++t) {
            float qpL_ = fmaxf(pL, QLB), qpU_ = fmaxf(pU, QLB);
            {
                int tn = (t + 1 < NSTEPS) ? t + 1 : t;
                const float* row = qp + (size_t)tn * NN;
                pL = __ldg(row + gidL);
                if (has_up) pU = __ldg(row + gidU);
            }
            float bL_, c1L, bU = 0.0f, c1U = 0.0f;
            phase_a(cL, qL, itL, qpL_, bL_, c1L);
            if (has_up) phase_a(cU, qU, itU, qpU_, bU, c1U);
            // poll own 2 children (relaxed: flag+payload share the word; loads pipeline)
            unsigned long long vA, vB;
            do {
                asm volatile("ld.relaxed.gpu.global.b64 %0, [%1];"
                             : "=l"(vA) : "l"(poll) : "memory");
                asm volatile("ld.relaxed.gpu.global.b64 %0, [%1];"
                             : "=l"(vB) : "l"(poll + 1) : "memory");
            } while ((vA >> 32) == 0ull || (vB >> 32) == 0ull);
            rA = __uint_as_float((unsigned)vA);
            rB = __uint_as_float((unsigned)vB);
            poll += pollstride;
            float q1L = fmaf(c1L, rA + rB, bL_);       // owned-level final (raw)
            itL = fmaxf(rA, QLB) + fmaxf(rB, QLB);
            qL = fmaxf(q1L, QLB);
            // capture for du==4 from q1L
            {
                float xa = __shfl_sync(FULLM, q1L, sCa);
                float xb = __shfl_sync(FULLM, q1L, sCb);
                if (has_up && du == 4) {
                    bU = fmaf(c1U, xa + xb, bU);
                    itU = fmaxf(xa, QLB) + fmaxf(xb, QLB);
                }
            }
            #pragma unroll
            for (int d = 3; d >= 0; --d) {
                float ya = __shfl_sync(FULLM, bU, sUa);
                float yb = __shfl_sync(FULLM, bU, sUb);
                if (has_up && du == d) {
                    bU = fmaf(c1U, ya + yb, bU);
                    itU = fmaxf(ya, QLB) + fmaxf(yb, QLB);
                }
            }
            if (has_up) qU = fmaxf(bU, QLB);
            if (lane == 0) {                           // subtree root (L9 / L15)
                pub_relaxed(pub, bU);
                pub += pubstride;
            }
        }
    } else {
        // ================= T4: level 16 root =================
        if (lane != 0) return;
        const int gid = 131070;
        NodeC cR = make_node(gid, nr, qsr, len, slope, twp, ssp, xp);
        float q = qp[gid];
        float rA = qp[131068], rB = qp[131069];        // level-15 q0 raw
        float itn = rA + rB;
        float p = q;
        const unsigned long long* poll = g3;
        out[0] = fmaxf(qp[131070], QLB);

        for (int t = 0; t < NSTEPS; ++t) {
            float qpc = fmaxf(p, QLB);
            {
                int tn = (t + 1 < NSTEPS) ? t + 1 : t;
                p = __ldg(qp + (size_t)tn * NN + gid);
            }
            float b, c1;
            phase_a(cR, q, itn, qpc, b, c1);
            unsigned long long vA, vB;
            do {
                asm volatile("ld.relaxed.gpu.global.b64 %0, [%1];"
                             : "=l"(vA) : "l"(poll) : "memory");
                asm volatile("ld.relaxed.gpu.global.b64 %0, [%1];"
                             : "=l"(vB) : "l"(poll + 1) : "memory");
            } while ((vA >> 32) == 0ull || (vB >> 32) == 0ull);
            rA = __uint_as_float((unsigned)vA);
            rB = __uint_as_float((unsigned)vB);
            poll += 2;
            float q1 = fmaf(c1, rA + rB, b);           // root final (raw)
            itn = fmaxf(rA, QLB) + fmaxf(rB, QLB);
            q = fmaxf(q1, QLB);
            out[t + 1] = q;
        }
    }
}

extern "C" void kernel_launch(void* const* d_in, const int* in_sizes, int n_in,
                              void* d_out, int out_size)
{
    const float* qp    = (const float*)d_in[0];
    const float* nr    = (const float*)d_in[1];
    const float* qsr   = (const float*)d_in[2];
    const float* len   = (const float*)d_in[3];
    const float* slope = (const float*)d_in[4];
    const float* twp   = (const float*)d_in[5];
    const float* ssp   = (const float*)d_in[6];
    const float* xp    = (const float*)d_in[7];
    float* out = (float*)d_out;

    init_kernel<<<(NSTEPS * 8192 + 255) / 256, 256>>>();
    route_kernel<<<4227, 32>>>(qp, nr, qsr, len, slope, twp, ssp, xp, out);
}